// round 6
// baseline (speedup 1.0000x reference)
#include <cuda_runtime.h>
#include <cstdint>

// x: [8192,3] f32, y: [8192,3] f32, y_fea: [8192,16] f32 -> out [8192,16] f32
// k_sigma: exp(-200 d2)=e3^16, exp(-50 d2)=e3^4, exp(-12.5 d2)=e3; w=0.3/0.3/0.4
// Transposed GEMM: out^T[c][n] = sum_m F^T[c][m] * K^T[m][n]
//   A (16x8) = y_fea^T (staged, tf32-RNA-rounded), B (8x8) = generated K (tf32-
//   truncated via AND mask; row-sums use the SAME truncated bits -> bias cancels).

#define N_PTS    8192
#define M_PTS    8192
#define KB_SPLIT 8
#define M_PER_CTA (M_PTS / KB_SPLIT)     // 1024
#define MS       128                     // m-tile staged in SMEM
#define NSTAGE   (M_PER_CTA / MS)        // 8
#define THREADS  256                     // 8 warps x 8 n-rows = 64 n per CTA
#define YFS_STR  24                      // padded row stride (floats), bank-conflict-free

typedef unsigned long long ull;

// static scratch (allocations are forbidden)
__device__ float g_U[3][KB_SPLIT][N_PTS][16];   // 12.6 MB
__device__ float g_S[3][KB_SPLIT][N_PTS];       //  0.8 MB

__device__ __forceinline__ ull pack2(float a, float b) {
    ull r; asm("mov.b64 %0, {%1, %2};" : "=l"(r) : "f"(a), "f"(b)); return r;
}
__device__ __forceinline__ float2 unpack2(ull v) {
    float2 f; asm("mov.b64 {%0, %1}, %2;" : "=f"(f.x), "=f"(f.y) : "l"(v)); return f;
}
__device__ __forceinline__ ull add2(ull a, ull b) {
    ull r; asm("add.rn.f32x2 %0, %1, %2;" : "=l"(r) : "l"(a), "l"(b)); return r;
}
__device__ __forceinline__ ull mul2(ull a, ull b) {
    ull r; asm("mul.rn.f32x2 %0, %1, %2;" : "=l"(r) : "l"(a), "l"(b)); return r;
}
__device__ __forceinline__ ull fma2v(ull a, ull b, ull c) {
    ull r; asm("fma.rn.f32x2 %0, %1, %2, %3;" : "=l"(r) : "l"(a), "l"(b), "l"(c)); return r;
}
__device__ __forceinline__ float ex2f(float x) {
    float r; asm("ex2.approx.f32 %0, %1;" : "=f"(r) : "f"(x)); return r;
}
__device__ __forceinline__ uint32_t tf32r(float f) {
    uint32_t u; asm("cvt.rna.tf32.f32 %0, %1;" : "=r"(u) : "f"(f)); return u;
}

// D (16x8) += A (16x8, rows=c, cols=k=m) * B (8x8, rows=k=m, cols=n)
__device__ __forceinline__ void mma_tf32(float* D,
                                         float a0, float a1, float a2, float a3,
                                         uint32_t b0, uint32_t b1) {
    asm volatile(
        "mma.sync.aligned.m16n8k8.row.col.f32.tf32.tf32.f32 "
        "{%0,%1,%2,%3}, {%4,%5,%6,%7}, {%8,%9}, {%0,%1,%2,%3};"
        : "+f"(D[0]), "+f"(D[1]), "+f"(D[2]), "+f"(D[3])
        : "r"(__float_as_uint(a0)), "r"(__float_as_uint(a1)),
          "r"(__float_as_uint(a2)), "r"(__float_as_uint(a3)),
          "r"(b0), "r"(b1));
}

__global__ __launch_bounds__(THREADS, 3) void mgsc_pass1(
    const float* __restrict__ x,
    const float* __restrict__ y,
    const float* __restrict__ yfea)
{
    // y staged as interleaved (m, m+4) pairs: ysw[pair][comp 0..3] where
    // comps = { y'0, y'1, y'2, b }, y' = -2*Cexp*y, b = Cexp*|y|^2.
    __shared__ __align__(16) ull   ysw[MS / 2][4];       //  2 KB
    __shared__ __align__(16) float yfs[MS * YFS_STR];    // 12 KB (tf32-rounded y_fea)

    const int tid  = threadIdx.x;
    const int warp = tid >> 5;
    const int lane = tid & 31;
    const int g    = lane >> 2;          // 0..7
    const int t    = lane & 3;           // 0..3
    const int nb   = blockIdx.x * 64 + warp * 8;
    const int n    = nb + g;             // this thread's single n-row
    const int mstart = blockIdx.y * M_PER_CTA;
    const int kb   = blockIdx.y;

    const float Cexp = -12.5f * 1.44269504088896340736f;

    const float x0 = x[n*3+0], x1 = x[n*3+1], x2 = x[n*3+2];
    const float a  = Cexp * (x0*x0 + x1*x1 + x2*x2);
    const ull X0 = pack2(x0, x0), X1 = pack2(x1, x1), X2 = pack2(x2, x2);
    const ull AP = pack2(a, a);
    const ull MASK = 0xffffe000ffffe000ull;   // tf32 truncation, both lanes

    float D[3][4];
    ull S[3] = {0, 0, 0};
    #pragma unroll
    for (int s = 0; s < 3; s++)
        #pragma unroll
        for (int q = 0; q < 4; q++) D[s][q] = 0.f;

    for (int st = 0; st < NSTAGE; st++) {
        if (st) __syncthreads();
        // ---- stage y (transformed) ----
        if (tid < MS) {
            const int m = mstart + st * MS + tid;
            const float y0 = y[m*3+0], y1 = y[m*3+1], y2 = y[m*3+2];
            const float b  = Cexp * (y0*y0 + y1*y1 + y2*y2);
            const float sc = -2.0f * Cexp;
            const int p = (tid >> 3) * 4 + (tid & 3);
            const int h = (tid >> 2) & 1;
            float* w = (float*)&ysw[p][0];
            w[0*2+h] = sc * y0;
            w[1*2+h] = sc * y1;
            w[2*2+h] = sc * y2;
            w[3*2+h] = b;
        }
        // ---- stage y_fea (tf32-rounded, padded stride) ----
        {
            const float4* src = reinterpret_cast<const float4*>(
                yfea + (size_t)(mstart + st * MS) * 16);
            #pragma unroll
            for (int q = 0; q < 2; q++) {
                const int idx = tid + q * 256;      // 0..511 float4s
                float4 v = src[idx];
                v.x = __uint_as_float(tf32r(v.x));
                v.y = __uint_as_float(tf32r(v.y));
                v.z = __uint_as_float(tf32r(v.z));
                v.w = __uint_as_float(tf32r(v.w));
                const int m  = idx >> 2;
                const int c4 = idx & 3;
                *reinterpret_cast<float4*>(yfs + m * YFS_STR + c4 * 4) = v;
            }
        }
        __syncthreads();

        #pragma unroll 4
        for (int c8 = 0; c8 < MS / 8; c8++) {
            // packed y operands for m = (c8*8+t, c8*8+t+4): 2x LDS.128
            const ulonglong2 q0 = *reinterpret_cast<const ulonglong2*>(&ysw[c8*4 + t][0]);
            const ulonglong2 q1 = *reinterpret_cast<const ulonglong2*>(&ysw[c8*4 + t][2]);

            ull arg = add2(AP, q1.y);            // a + b_m
            arg = fma2v(X0, q0.x, arg);
            arg = fma2v(X1, q0.y, arg);
            arg = fma2v(X2, q1.x, arg);

            const float2 fa = unpack2(arg);
            const ull e3 = pack2(ex2f(fa.x), ex2f(fa.y));
            const ull qq = mul2(e3, e3);
            const ull e2 = mul2(qq, qq);
            const ull rr = mul2(e2, e2);
            const ull e1 = mul2(rr, rr);

            // tf32-truncate (same bits feed the MMA and the row-sums)
            const ull k1 = e1 & MASK, k2 = e2 & MASK, k3 = e3 & MASK;
            S[0] = add2(S[0], k1);
            S[1] = add2(S[1], k2);
            S[2] = add2(S[2], k3);

            // A fragments: F^T rows c = {g, g+8}, cols k = {t, t+4}
            const float* ap0 = yfs + (c8 * 8 + t) * YFS_STR;
            const float* ap1 = ap0 + 4 * YFS_STR;
            const float a0 = ap0[g], a1 = ap0[g + 8];
            const float a2 = ap1[g], a3 = ap1[g + 8];

            const float2 k1f = unpack2(k1);
            const float2 k2f = unpack2(k2);
            const float2 k3f = unpack2(k3);
            mma_tf32(D[0], a0, a1, a2, a3,
                     __float_as_uint(k1f.x), __float_as_uint(k1f.y));
            mma_tf32(D[1], a0, a1, a2, a3,
                     __float_as_uint(k2f.x), __float_as_uint(k2f.y));
            mma_tf32(D[2], a0, a1, a2, a3,
                     __float_as_uint(k3f.x), __float_as_uint(k3f.y));
        }
    }

    // ---- row-sums: horizontal add + reduce over the 4 t-lanes of this n ----
    #pragma unroll
    for (int s = 0; s < 3; s++) {
        const float2 v = unpack2(S[s]);
        float rs = v.x + v.y;
        rs += __shfl_xor_sync(0xffffffffu, rs, 1);
        rs += __shfl_xor_sync(0xffffffffu, rs, 2);
        if (t == 0) g_S[s][kb][n] = rs;
    }
    // ---- D -> g_U : d0=(c=g, n=nb+2t) d1=(g, nb+2t+1) d2=(g+8, 2t) d3=(g+8, 2t+1)
    const int n0 = nb + 2 * t, n1 = n0 + 1;
    #pragma unroll
    for (int s = 0; s < 3; s++) {
        g_U[s][kb][n0][g]     = D[s][0];
        g_U[s][kb][n1][g]     = D[s][1];
        g_U[s][kb][n0][g + 8] = D[s][2];
        g_U[s][kb][n1][g + 8] = D[s][3];
    }
}

__global__ __launch_bounds__(256) void mgsc_reduce(float* __restrict__ out)
{
    // thread per (n, c): 131072 threads -> 512 blocks
    const int idx = blockIdx.x * 256 + threadIdx.x;
    const int n = idx >> 4;
    const int c = idx & 15;

    const float w[3] = {0.3f, 0.3f, 0.4f};
    float acc = 0.f;
    #pragma unroll
    for (int s = 0; s < 3; s++) {
        float u = 0.f, sm = 0.f;
        #pragma unroll
        for (int k = 0; k < KB_SPLIT; k++) {
            u  += g_U[s][k][n][c];
            sm += g_S[s][k][n];
        }
        acc += w[s] * u / sm;
    }
    out[idx] = acc;
}

extern "C" void kernel_launch(void* const* d_in, const int* in_sizes, int n_in,
                              void* d_out, int out_size)
{
    const float* x    = (const float*)d_in[0];
    const float* y    = (const float*)d_in[1];
    const float* yfea = (const float*)d_in[2];
    float*       out  = (float*)d_out;

    dim3 grid(N_PTS / 64, KB_SPLIT);         // (128, 8) = 1024 CTAs
    mgsc_pass1<<<grid, THREADS>>>(x, y, yfea);
    mgsc_reduce<<<(N_PTS * 16) / 256, 256>>>(out);   // 512 blocks
}

// round 7
// speedup vs baseline: 1.2081x; 1.2081x over previous
#include <cuda_runtime.h>
#include <cstdint>

// x: [8192,3] f32, y: [8192,3] f32, y_fea: [8192,16] f32 -> out [8192,16] f32
// k_sigma: exp(-200 d2)=e3^16, exp(-50 d2)=e3^4, exp(-12.5 d2)=e3; w=0.3/0.3/0.4
// Transposed GEMM at the HMMA floor: out^T[c][n] = sum_m F^T[c][m] * K^T[m][n]
//   A (16x8) = y_fea^T staged PRE-PERMUTED in fragment order (1 LDS.128/chunk),
//   B (8x8)  = generated K, tf32-truncated via AND; row-sums use the SAME bits.
//   Two n-groups per warp share A and ysw loads.

#define N_PTS    8192
#define M_PTS    8192
#define KB_SPLIT 16
#define M_PER_CTA (M_PTS / KB_SPLIT)     // 512
#define MS       256                     // m-tile staged in SMEM
#define NSTAGE   (M_PER_CTA / MS)        // 2
#define THREADS  256                     // 8 warps x 16 n = 128 n per CTA

typedef unsigned long long ull;

// static scratch (allocations are forbidden)
__device__ float g_U[3][KB_SPLIT][N_PTS][16];   // 25.2 MB (L2-resident)
__device__ float g_S[3][KB_SPLIT][N_PTS];       //  1.6 MB

__device__ __forceinline__ ull pack2(float a, float b) {
    ull r; asm("mov.b64 %0, {%1, %2};" : "=l"(r) : "f"(a), "f"(b)); return r;
}
__device__ __forceinline__ float2 unpack2(ull v) {
    float2 f; asm("mov.b64 {%0, %1}, %2;" : "=f"(f.x), "=f"(f.y) : "l"(v)); return f;
}
__device__ __forceinline__ ull add2(ull a, ull b) {
    ull r; asm("add.rn.f32x2 %0, %1, %2;" : "=l"(r) : "l"(a), "l"(b)); return r;
}
__device__ __forceinline__ ull mul2(ull a, ull b) {
    ull r; asm("mul.rn.f32x2 %0, %1, %2;" : "=l"(r) : "l"(a), "l"(b)); return r;
}
__device__ __forceinline__ ull fma2v(ull a, ull b, ull c) {
    ull r; asm("fma.rn.f32x2 %0, %1, %2, %3;" : "=l"(r) : "l"(a), "l"(b), "l"(c)); return r;
}
__device__ __forceinline__ float ex2f(float x) {
    float r; asm("ex2.approx.f32 %0, %1;" : "=f"(r) : "f"(x)); return r;
}
__device__ __forceinline__ uint32_t tf32r(float f) {
    uint32_t u; asm("cvt.rna.tf32.f32 %0, %1;" : "=r"(u) : "f"(f)); return u;
}

// D (16c x 8n) += A (16x8, rows=c, k=m) * B (8x8, k=m, cols=n)
__device__ __forceinline__ void mma_tf32(float* D, const float4& A,
                                         uint32_t b0, uint32_t b1) {
    asm volatile(
        "mma.sync.aligned.m16n8k8.row.col.f32.tf32.tf32.f32 "
        "{%0,%1,%2,%3}, {%4,%5,%6,%7}, {%8,%9}, {%0,%1,%2,%3};"
        : "+f"(D[0]), "+f"(D[1]), "+f"(D[2]), "+f"(D[3])
        : "r"(__float_as_uint(A.x)), "r"(__float_as_uint(A.y)),
          "r"(__float_as_uint(A.z)), "r"(__float_as_uint(A.w)),
          "r"(b0), "r"(b1));
}

__global__ __launch_bounds__(THREADS, 3) void mgsc_pass1(
    const float* __restrict__ x,
    const float* __restrict__ y,
    const float* __restrict__ yfea)
{
    // ysw[pair][comp]: interleaved (m, m+4) pairs; comps { y'0, y'1, y'2, b },
    // y' = -2*Cexp*y, b = Cexp*|y|^2.
    __shared__ __align__(16) ull   ysw[MS / 2][4];            //  4 KB
    // yfrag[c8][lane][slot]: A-fragment order. lane=g*4+t;
    // slot0=F[m(t)][g] slot1=F[m(t)][g+8] slot2=F[m(t+4)][g] slot3=F[m(t+4)][g+8]
    __shared__ __align__(16) float yfrag[(MS / 8) * 32 * 4];  // 16 KB

    const int tid  = threadIdx.x;
    const int warp = tid >> 5;
    const int lane = tid & 31;
    const int g    = lane >> 2;          // 0..7
    const int t    = lane & 3;           // 0..3
    const int nbA  = blockIdx.x * 128 + warp * 16;   // group A: n cols nbA..nbA+7
    const int nbB  = nbA + 8;                        // group B: next 8 cols
    const int mstart = blockIdx.y * M_PER_CTA;
    const int kb   = blockIdx.y;

    const float Cexp = -12.5f * 1.44269504088896340736f;

    // per-thread x constants for the two n-groups (n = nb + g)
    const int nA = nbA + g, nB = nbB + g;
    const float xa0 = x[nA*3+0], xa1 = x[nA*3+1], xa2 = x[nA*3+2];
    const float xb0 = x[nB*3+0], xb1 = x[nB*3+1], xb2 = x[nB*3+2];
    const float aa = Cexp * (xa0*xa0 + xa1*xa1 + xa2*xa2);
    const float ab = Cexp * (xb0*xb0 + xb1*xb1 + xb2*xb2);
    const ull XA0 = pack2(xa0, xa0), XA1 = pack2(xa1, xa1), XA2 = pack2(xa2, xa2);
    const ull XB0 = pack2(xb0, xb0), XB1 = pack2(xb1, xb1), XB2 = pack2(xb2, xb2);
    const ull APA = pack2(aa, aa),   APB = pack2(ab, ab);
    const ull MASK = 0xffffe000ffffe000ull;   // tf32 truncation, both lanes

    float DA[3][4], DB[3][4];
    ull SA[3] = {0,0,0}, SB[3] = {0,0,0};
    #pragma unroll
    for (int s = 0; s < 3; s++)
        #pragma unroll
        for (int q = 0; q < 4; q++) { DA[s][q] = 0.f; DB[s][q] = 0.f; }

    for (int st = 0; st < NSTAGE; st++) {
        if (st) __syncthreads();
        // ---- stage y (transformed), one m per thread ----
        {
            const int m = mstart + st * MS + tid;
            const float y0 = y[m*3+0], y1 = y[m*3+1], y2 = y[m*3+2];
            const float b  = Cexp * (y0*y0 + y1*y1 + y2*y2);
            const float sc = -2.0f * Cexp;
            const int p = (tid >> 3) * 4 + (tid & 3);
            const int h = (tid >> 2) & 1;
            float* w = (float*)&ysw[p][0];
            w[0*2+h] = sc * y0;
            w[1*2+h] = sc * y1;
            w[2*2+h] = sc * y2;
            w[3*2+h] = b;
        }
        // ---- stage y_fea tf32-RNA-rounded, permuted into fragment order ----
        {
            const float4* src = reinterpret_cast<const float4*>(
                yfea + (size_t)(mstart + st * MS) * 16);
            #pragma unroll
            for (int q = 0; q < 4; q++) {
                const int idx = tid + q * 256;      // 0..1023 float4s
                float4 v = src[idx];
                const int m  = idx >> 2;            // local m 0..255
                const int c4 = (idx & 3) * 4;       // first c of this float4
                const int c8 = m >> 3, tt = m & 3, mh = (m >> 2) & 1;
                const int sl = 2 * mh;              // + (c>>3)
                float vv[4] = {__uint_as_float(tf32r(v.x)), __uint_as_float(tf32r(v.y)),
                               __uint_as_float(tf32r(v.z)), __uint_as_float(tf32r(v.w))};
                #pragma unroll
                for (int j = 0; j < 4; j++) {
                    const int c  = c4 + j;
                    const int gl = c & 7, ch = c >> 3;
                    yfrag[(c8 * 32 + gl * 4 + tt) * 4 + sl + ch] = vv[j];
                }
            }
        }
        __syncthreads();

        #pragma unroll 4
        for (int c8 = 0; c8 < MS / 8; c8++) {
            // shared operands
            const float4 AF = *reinterpret_cast<const float4*>(
                &yfrag[(c8 * 32 + lane) * 4]);                       // 1 LDS.128
            const ulonglong2 q0 = *reinterpret_cast<const ulonglong2*>(&ysw[c8*4 + t][0]);
            const ulonglong2 q1 = *reinterpret_cast<const ulonglong2*>(&ysw[c8*4 + t][2]);

            // ---- group A ----
            {
                ull arg = add2(APA, q1.y);
                arg = fma2v(XA0, q0.x, arg);
                arg = fma2v(XA1, q0.y, arg);
                arg = fma2v(XA2, q1.x, arg);
                const float2 fa = unpack2(arg);
                const ull e3 = pack2(ex2f(fa.x), ex2f(fa.y));
                const ull qq = mul2(e3, e3);
                const ull e2 = mul2(qq, qq);
                const ull rr = mul2(e2, e2);
                const ull e1 = mul2(rr, rr);
                const ull k1 = e1 & MASK, k2 = e2 & MASK, k3 = e3 & MASK;
                SA[0] = add2(SA[0], k1);
                SA[1] = add2(SA[1], k2);
                SA[2] = add2(SA[2], k3);
                const float2 k1f = unpack2(k1), k2f = unpack2(k2), k3f = unpack2(k3);
                mma_tf32(DA[0], AF, __float_as_uint(k1f.x), __float_as_uint(k1f.y));
                mma_tf32(DA[1], AF, __float_as_uint(k2f.x), __float_as_uint(k2f.y));
                mma_tf32(DA[2], AF, __float_as_uint(k3f.x), __float_as_uint(k3f.y));
            }
            // ---- group B ----
            {
                ull arg = add2(APB, q1.y);
                arg = fma2v(XB0, q0.x, arg);
                arg = fma2v(XB1, q0.y, arg);
                arg = fma2v(XB2, q1.x, arg);
                const float2 fb = unpack2(arg);
                const ull e3 = pack2(ex2f(fb.x), ex2f(fb.y));
                const ull qq = mul2(e3, e3);
                const ull e2 = mul2(qq, qq);
                const ull rr = mul2(e2, e2);
                const ull e1 = mul2(rr, rr);
                const ull k1 = e1 & MASK, k2 = e2 & MASK, k3 = e3 & MASK;
                SB[0] = add2(SB[0], k1);
                SB[1] = add2(SB[1], k2);
                SB[2] = add2(SB[2], k3);
                const float2 k1f = unpack2(k1), k2f = unpack2(k2), k3f = unpack2(k3);
                mma_tf32(DB[0], AF, __float_as_uint(k1f.x), __float_as_uint(k1f.y));
                mma_tf32(DB[1], AF, __float_as_uint(k2f.x), __float_as_uint(k2f.y));
                mma_tf32(DB[2], AF, __float_as_uint(k3f.x), __float_as_uint(k3f.y));
            }
        }
    }

    // ---- epilogue: row-sums (4 t-lanes per n) and D scatter ----
    #pragma unroll
    for (int s = 0; s < 3; s++) {
        float2 v = unpack2(SA[s]);
        float rs = v.x + v.y;
        rs += __shfl_xor_sync(0xffffffffu, rs, 1);
        rs += __shfl_xor_sync(0xffffffffu, rs, 2);
        if (t == 0) g_S[s][kb][nA] = rs;
        v = unpack2(SB[s]);
        float rb = v.x + v.y;
        rb += __shfl_xor_sync(0xffffffffu, rb, 1);
        rb += __shfl_xor_sync(0xffffffffu, rb, 2);
        if (t == 0) g_S[s][kb][nB] = rb;
    }
    {
        const int a0 = nbA + 2*t, a1 = a0 + 1;
        const int b0 = nbB + 2*t, b1 = b0 + 1;
        #pragma unroll
        for (int s = 0; s < 3; s++) {
            g_U[s][kb][a0][g]     = DA[s][0];
            g_U[s][kb][a1][g]     = DA[s][1];
            g_U[s][kb][a0][g + 8] = DA[s][2];
            g_U[s][kb][a1][g + 8] = DA[s][3];
            g_U[s][kb][b0][g]     = DB[s][0];
            g_U[s][kb][b1][g]     = DB[s][1];
            g_U[s][kb][b0][g + 8] = DB[s][2];
            g_U[s][kb][b1][g + 8] = DB[s][3];
        }
    }
}

__global__ __launch_bounds__(256) void mgsc_reduce(float* __restrict__ out)
{
    // thread per (n, c): 131072 threads -> 512 blocks
    const int idx = blockIdx.x * 256 + threadIdx.x;
    const int n = idx >> 4;
    const int c = idx & 15;

    const float w[3] = {0.3f, 0.3f, 0.4f};
    float acc = 0.f;
    #pragma unroll
    for (int s = 0; s < 3; s++) {
        float u = 0.f, sm = 0.f;
        #pragma unroll
        for (int k = 0; k < KB_SPLIT; k++) {
            u  += g_U[s][k][n][c];
            sm += g_S[s][k][n];
        }
        acc += w[s] * u / sm;
    }
    out[idx] = acc;
}

extern "C" void kernel_launch(void* const* d_in, const int* in_sizes, int n_in,
                              void* d_out, int out_size)
{
    const float* x    = (const float*)d_in[0];
    const float* y    = (const float*)d_in[1];
    const float* yfea = (const float*)d_in[2];
    float*       out  = (float*)d_out;

    dim3 grid(N_PTS / 128, KB_SPLIT);        // (64, 16) = 1024 CTAs
    mgsc_pass1<<<grid, THREADS>>>(x, y, yfea);
    mgsc_reduce<<<(N_PTS * 16) / 256, 256>>>(out);   // 512 blocks
}

// round 8
// speedup vs baseline: 1.4131x; 1.1697x over previous
#include <cuda_runtime.h>
#include <cstdint>

// x: [8192,3] f32, y: [8192,3] f32, y_fea: [8192,16] f32 -> out [8192,16] f32
// k_sigma: exp(-200 d2)=e3^16, exp(-50 d2)=e3^4, exp(-12.5 d2)=e3; w=0.3/0.3/0.4
// Transposed GEMM, fp16 m16n8k16: out^T[c][n] = sum_m F^T[c][m] * K^T[m][n]
//   A (16x16) = y_fea^T, fp16, staged pre-permuted in fragment order (1 LDS.128)
//   B (16x8)  = generated kernel, fp16x2 via cvt.rn.f16x2.f32 (RN, unbiased)
//   Row-sums: f32 packed adds of the unrounded e-values (RN bias averages out).

#define N_PTS    8192
#define M_PTS    8192
#define KB_SPLIT 16
#define M_PER_CTA (M_PTS / KB_SPLIT)     // 512
#define MS       256                     // m-tile staged in SMEM
#define NSTAGE   (M_PER_CTA / MS)        // 2
#define THREADS  256                     // 8 warps x 16 n = 128 n per CTA

typedef unsigned long long ull;

// static scratch (allocations are forbidden)
__device__ float g_U[3][KB_SPLIT][N_PTS][16];   // 25.2 MB
__device__ float g_S[3][KB_SPLIT][N_PTS];       //  1.6 MB

__device__ __forceinline__ ull pack2(float a, float b) {
    ull r; asm("mov.b64 %0, {%1, %2};" : "=l"(r) : "f"(a), "f"(b)); return r;
}
__device__ __forceinline__ float2 unpack2(ull v) {
    float2 f; asm("mov.b64 {%0, %1}, %2;" : "=f"(f.x), "=f"(f.y) : "l"(v)); return f;
}
__device__ __forceinline__ ull add2(ull a, ull b) {
    ull r; asm("add.rn.f32x2 %0, %1, %2;" : "=l"(r) : "l"(a), "l"(b)); return r;
}
__device__ __forceinline__ ull mul2(ull a, ull b) {
    ull r; asm("mul.rn.f32x2 %0, %1, %2;" : "=l"(r) : "l"(a), "l"(b)); return r;
}
__device__ __forceinline__ ull fma2v(ull a, ull b, ull c) {
    ull r; asm("fma.rn.f32x2 %0, %1, %2, %3;" : "=l"(r) : "l"(a), "l"(b), "l"(c)); return r;
}
__device__ __forceinline__ float ex2f(float x) {
    float r; asm("ex2.approx.f32 %0, %1;" : "=f"(r) : "f"(x)); return r;
}
// d = { lo: cvt(lo), hi: cvt(hi) }  (first PTX source -> high half)
__device__ __forceinline__ uint32_t f16x2(float hi, float lo) {
    uint32_t d; asm("cvt.rn.f16x2.f32 %0, %1, %2;" : "=r"(d) : "f"(hi), "f"(lo));
    return d;
}
// packed f32x2 -> fp16x2 (x lane -> low half)
__device__ __forceinline__ uint32_t cvt2h(ull v) {
    const float2 f = unpack2(v);
    return f16x2(f.y, f.x);
}

// D (16c x 8n) += A (16x16 fp16, rows=c, k=m) * B (16x8 fp16, k=m, cols=n)
__device__ __forceinline__ void mma_f16(float* D, const uint4& A,
                                        uint32_t b0, uint32_t b1) {
    asm volatile(
        "mma.sync.aligned.m16n8k16.row.col.f32.f16.f16.f32 "
        "{%0,%1,%2,%3}, {%4,%5,%6,%7}, {%8,%9}, {%0,%1,%2,%3};"
        : "+f"(D[0]), "+f"(D[1]), "+f"(D[2]), "+f"(D[3])
        : "r"(A.x), "r"(A.y), "r"(A.z), "r"(A.w), "r"(b0), "r"(b1));
}

__global__ __launch_bounds__(THREADS, 3) void mgsc_pass1(
    const float* __restrict__ x,
    const float* __restrict__ y,
    const float* __restrict__ yfea)
{
    // ysw[pair]: consecutive (m=2p, m=2p+1) pairs; 4 u64 comps { y'0, y'1, y'2, b }
    // with y' = -2*Cexp*y, b = Cexp*|y|^2; lane x = even m, lane y = odd m.
    __shared__ __align__(16) ull ysw[MS / 2][4];              //  4 KB
    // yfrag[c16][lane][reg 0..3]: fp16x2 A-fragments in m16n8k16 order.
    // lane = g*4+t; reg r: c = g + 8*(r&1), ml = 2t + 8*(r>>1); pair (ml, ml+1).
    __shared__ __align__(16) uint32_t yfrag[(MS / 16) * 32 * 4];   // 8 KB

    const int tid  = threadIdx.x;
    const int warp = tid >> 5;
    const int lane = tid & 31;
    const int g    = lane >> 2;          // 0..7
    const int t    = lane & 3;           // 0..3
    const int nbA  = blockIdx.x * 128 + warp * 16;
    const int nbB  = nbA + 8;
    const int mstart = blockIdx.y * M_PER_CTA;
    const int kb   = blockIdx.y;

    const float Cexp = -12.5f * 1.44269504088896340736f;

    const int nA = nbA + g, nB = nbB + g;
    const float xa0 = x[nA*3+0], xa1 = x[nA*3+1], xa2 = x[nA*3+2];
    const float xb0 = x[nB*3+0], xb1 = x[nB*3+1], xb2 = x[nB*3+2];
    const float aa = Cexp * (xa0*xa0 + xa1*xa1 + xa2*xa2);
    const float ab = Cexp * (xb0*xb0 + xb1*xb1 + xb2*xb2);
    const ull XA0 = pack2(xa0, xa0), XA1 = pack2(xa1, xa1), XA2 = pack2(xa2, xa2);
    const ull XB0 = pack2(xb0, xb0), XB1 = pack2(xb1, xb1), XB2 = pack2(xb2, xb2);
    const ull APA = pack2(aa, aa),   APB = pack2(ab, ab);

    float DA[3][4], DB[3][4];
    ull SA[3] = {0,0,0}, SB[3] = {0,0,0};
    #pragma unroll
    for (int s = 0; s < 3; s++)
        #pragma unroll
        for (int q = 0; q < 4; q++) { DA[s][q] = 0.f; DB[s][q] = 0.f; }

    for (int st = 0; st < NSTAGE; st++) {
        if (st) __syncthreads();
        // ---- stage y: one consecutive (m, m+1) pair per thread (tid < 128) ----
        if (tid < MS / 2) {
            const int m0 = mstart + st * MS + 2 * tid;
            const float2 l0 = *reinterpret_cast<const float2*>(&y[m0*3]);
            const float2 l1 = *reinterpret_cast<const float2*>(&y[m0*3+2]);
            const float2 l2 = *reinterpret_cast<const float2*>(&y[m0*3+4]);
            const float e0 = l0.x, e1v = l0.y, e2v = l1.x;   // even m
            const float o0 = l1.y, o1v = l2.x, o2v = l2.y;   // odd m
            const float sc = -2.0f * Cexp;
            const float be = Cexp * (e0*e0 + e1v*e1v + e2v*e2v);
            const float bo = Cexp * (o0*o0 + o1v*o1v + o2v*o2v);
            ull* w = &ysw[tid][0];
            w[0] = pack2(sc * e0,  sc * o0);
            w[1] = pack2(sc * e1v, sc * o1v);
            w[2] = pack2(sc * e2v, sc * o2v);
            w[3] = pack2(be, bo);
        }
        // ---- stage y_fea as fp16 A-fragments: thread -> (blk, 2 lanes) ----
        {
            const int blk = tid >> 4;
            const int l0  = (tid & 15) * 2;
            const int mb  = mstart + st * MS + blk * 16;
            #pragma unroll
            for (int j = 0; j < 2; j++) {
                const int l  = l0 + j;
                const int gg = l >> 2, tt = l & 3;
                uint4 regs;
                uint32_t* rp = &regs.x;
                #pragma unroll
                for (int r = 0; r < 4; r++) {
                    const int c  = gg + 8 * (r & 1);
                    const int m  = mb + 2 * tt + 8 * (r >> 1);
                    rp[r] = f16x2(yfea[(m + 1) * 16 + c], yfea[m * 16 + c]);
                }
                *reinterpret_cast<uint4*>(&yfrag[(blk * 32 + l) * 4]) = regs;
            }
        }
        __syncthreads();

        #pragma unroll 4
        for (int c16 = 0; c16 < MS / 16; c16++) {
            const uint4 AF = *reinterpret_cast<const uint4*>(
                &yfrag[(c16 * 32 + lane) * 4]);                      // 1 LDS.128
            // chain 0: pair (2t, 2t+1); chain 1: pair (2t+8, 2t+9)
            const ulonglong2 p0a = *reinterpret_cast<const ulonglong2*>(&ysw[c16*8 + t][0]);
            const ulonglong2 p0b = *reinterpret_cast<const ulonglong2*>(&ysw[c16*8 + t][2]);
            const ulonglong2 p1a = *reinterpret_cast<const ulonglong2*>(&ysw[c16*8 + t + 4][0]);
            const ulonglong2 p1b = *reinterpret_cast<const ulonglong2*>(&ysw[c16*8 + t + 4][2]);

            // ================= group A =================
            {
                ull arg = add2(APA, p0b.y);
                arg = fma2v(XA0, p0a.x, arg);
                arg = fma2v(XA1, p0a.y, arg);
                arg = fma2v(XA2, p0b.x, arg);
                float2 f = unpack2(arg);
                const ull e3a = pack2(ex2f(f.x), ex2f(f.y));
                const ull qa  = mul2(e3a, e3a);
                const ull e2a = mul2(qa, qa);
                const ull ra  = mul2(e2a, e2a);
                const ull e1a = mul2(ra, ra);

                arg = add2(APA, p1b.y);
                arg = fma2v(XA0, p1a.x, arg);
                arg = fma2v(XA1, p1a.y, arg);
                arg = fma2v(XA2, p1b.x, arg);
                f = unpack2(arg);
                const ull e3b = pack2(ex2f(f.x), ex2f(f.y));
                const ull qb  = mul2(e3b, e3b);
                const ull e2b = mul2(qb, qb);
                const ull rb  = mul2(e2b, e2b);
                const ull e1b = mul2(rb, rb);

                SA[0] = add2(SA[0], add2(e1a, e1b));
                SA[1] = add2(SA[1], add2(e2a, e2b));
                SA[2] = add2(SA[2], add2(e3a, e3b));

                mma_f16(DA[0], AF, cvt2h(e1a), cvt2h(e1b));
                mma_f16(DA[1], AF, cvt2h(e2a), cvt2h(e2b));
                mma_f16(DA[2], AF, cvt2h(e3a), cvt2h(e3b));
            }
            // ================= group B =================
            {
                ull arg = add2(APB, p0b.y);
                arg = fma2v(XB0, p0a.x, arg);
                arg = fma2v(XB1, p0a.y, arg);
                arg = fma2v(XB2, p0b.x, arg);
                float2 f = unpack2(arg);
                const ull e3a = pack2(ex2f(f.x), ex2f(f.y));
                const ull qa  = mul2(e3a, e3a);
                const ull e2a = mul2(qa, qa);
                const ull ra  = mul2(e2a, e2a);
                const ull e1a = mul2(ra, ra);

                arg = add2(APB, p1b.y);
                arg = fma2v(XB0, p1a.x, arg);
                arg = fma2v(XB1, p1a.y, arg);
                arg = fma2v(XB2, p1b.x, arg);
                f = unpack2(arg);
                const ull e3b = pack2(ex2f(f.x), ex2f(f.y));
                const ull qb  = mul2(e3b, e3b);
                const ull e2b = mul2(qb, qb);
                const ull rb  = mul2(e2b, e2b);
                const ull e1b = mul2(rb, rb);

                SB[0] = add2(SB[0], add2(e1a, e1b));
                SB[1] = add2(SB[1], add2(e2a, e2b));
                SB[2] = add2(SB[2], add2(e3a, e3b));

                mma_f16(DB[0], AF, cvt2h(e1a), cvt2h(e1b));
                mma_f16(DB[1], AF, cvt2h(e2a), cvt2h(e2b));
                mma_f16(DB[2], AF, cvt2h(e3a), cvt2h(e3b));
            }
        }
    }

    // ---- row-sums: horizontal add + reduce over the 4 t-lanes of each n ----
    #pragma unroll
    for (int s = 0; s < 3; s++) {
        float2 v = unpack2(SA[s]);
        float rs = v.x + v.y;
        rs += __shfl_xor_sync(0xffffffffu, rs, 1);
        rs += __shfl_xor_sync(0xffffffffu, rs, 2);
        if (t == 0) g_S[s][kb][nA] = rs;
        v = unpack2(SB[s]);
        float rb = v.x + v.y;
        rb += __shfl_xor_sync(0xffffffffu, rb, 1);
        rb += __shfl_xor_sync(0xffffffffu, rb, 2);
        if (t == 0) g_S[s][kb][nB] = rb;
    }
    // ---- D -> g_U (same fragment layout as m16n8k8 for D) ----
    {
        const int a0 = nbA + 2*t, a1 = a0 + 1;
        const int b0 = nbB + 2*t, b1 = b0 + 1;
        #pragma unroll
        for (int s = 0; s < 3; s++) {
            g_U[s][kb][a0][g]     = DA[s][0];
            g_U[s][kb][a1][g]     = DA[s][1];
            g_U[s][kb][a0][g + 8] = DA[s][2];
            g_U[s][kb][a1][g + 8] = DA[s][3];
            g_U[s][kb][b0][g]     = DB[s][0];
            g_U[s][kb][b1][g]     = DB[s][1];
            g_U[s][kb][b0][g + 8] = DB[s][2];
            g_U[s][kb][b1][g + 8] = DB[s][3];
        }
    }
}

__global__ __launch_bounds__(256) void mgsc_reduce(float* __restrict__ out)
{
    // 2 threads per (n, c): each sums half the k-range, combine via shfl.
    const int idx  = blockIdx.x * 256 + threadIdx.x;   // 262144 threads
    const int pid  = idx >> 1;
    const int half = idx & 1;
    const int n = pid >> 4;
    const int c = pid & 15;
    const int k0 = half * (KB_SPLIT / 2);

    float u[3] = {0.f, 0.f, 0.f}, sm[3] = {0.f, 0.f, 0.f};
    #pragma unroll
    for (int k = 0; k < KB_SPLIT / 2; k++)
        #pragma unroll
        for (int s = 0; s < 3; s++) {
            u[s]  += g_U[s][k0 + k][n][c];
            sm[s] += g_S[s][k0 + k][n];
        }

    const float w[3] = {0.3f, 0.3f, 0.4f};
    float acc = 0.f;
    #pragma unroll
    for (int s = 0; s < 3; s++) {
        const float uu = u[s]  + __shfl_xor_sync(0xffffffffu, u[s],  1);
        const float ss = sm[s] + __shfl_xor_sync(0xffffffffu, sm[s], 1);
        acc += w[s] * uu / ss;
    }
    if (half == 0) out[pid] = acc;
}

extern "C" void kernel_launch(void* const* d_in, const int* in_sizes, int n_in,
                              void* d_out, int out_size)
{
    const float* x    = (const float*)d_in[0];
    const float* y    = (const float*)d_in[1];
    const float* yfea = (const float*)d_in[2];
    float*       out  = (float*)d_out;

    dim3 grid(N_PTS / 128, KB_SPLIT);        // (64, 16) = 1024 CTAs
    mgsc_pass1<<<grid, THREADS>>>(x, y, yfea);
    mgsc_reduce<<<(N_PTS * 16 * 2) / 256, 256>>>(out);   // 1024 blocks
}